// round 1
// baseline (speedup 1.0000x reference)
#include <cuda_runtime.h>
#include <math.h>

// Problem constants
#define B_    2
#define N_    1024
#define QD_   512
#define H_    8
#define DH_   64
#define SCALE_ 0.125f   // DH^-0.5

// ---------------- scratch (no allocation allowed) ----------------
__device__ float g_q [B_*N_*QD_];
__device__ float g_k [B_*N_*QD_];
__device__ float g_v [B_*N_*QD_];
__device__ float g_ao[B_*N_*QD_];
__device__ float g_m [N_];
__device__ float g_cnt[1];
__device__ float g_scale[2*QD_];
__device__ float g_shift[2*QD_];

// =================================================================
// GEMM: C[M,N] = A[M,K] * B[N,K]^T (+ bias[N]); M,N mult of 64, K mult of 16
// 256 threads, 64x64 tile, 4x4 microtile.
// =================================================================
__global__ __launch_bounds__(256) void gemm_nt(
    const float* __restrict__ A, const float* __restrict__ Bm,
    const float* __restrict__ bias, float* __restrict__ C,
    int M, int N, int K)
{
    __shared__ float As[16][64];
    __shared__ float Bs[16][64];
    const int tid  = threadIdx.x;
    const int bm   = blockIdx.y * 64;
    const int bn   = blockIdx.x * 64;
    const int tm   = (tid & 15) * 4;
    const int tn   = (tid >> 4) * 4;
    const int lrow = tid >> 2;
    const int lc4  = tid & 3;

    float acc[4][4];
#pragma unroll
    for (int i = 0; i < 4; i++)
#pragma unroll
        for (int j = 0; j < 4; j++) acc[i][j] = 0.f;

    const float4* Ap = (const float4*)(A  + (size_t)(bm + lrow) * K) + lc4;
    const float4* Bp = (const float4*)(Bm + (size_t)(bn + lrow) * K) + lc4;

    for (int k0 = 0; k0 < K; k0 += 16) {
        float4 a4 = Ap[k0 >> 2];
        float4 b4 = Bp[k0 >> 2];
        __syncthreads();
        As[lc4*4+0][lrow] = a4.x; As[lc4*4+1][lrow] = a4.y;
        As[lc4*4+2][lrow] = a4.z; As[lc4*4+3][lrow] = a4.w;
        Bs[lc4*4+0][lrow] = b4.x; Bs[lc4*4+1][lrow] = b4.y;
        Bs[lc4*4+2][lrow] = b4.z; Bs[lc4*4+3][lrow] = b4.w;
        __syncthreads();
#pragma unroll
        for (int kk = 0; kk < 16; kk++) {
            float4 av = *(const float4*)&As[kk][tm];
            float4 bv = *(const float4*)&Bs[kk][tn];
            acc[0][0] = fmaf(av.x, bv.x, acc[0][0]);
            acc[0][1] = fmaf(av.x, bv.y, acc[0][1]);
            acc[0][2] = fmaf(av.x, bv.z, acc[0][2]);
            acc[0][3] = fmaf(av.x, bv.w, acc[0][3]);
            acc[1][0] = fmaf(av.y, bv.x, acc[1][0]);
            acc[1][1] = fmaf(av.y, bv.y, acc[1][1]);
            acc[1][2] = fmaf(av.y, bv.z, acc[1][2]);
            acc[1][3] = fmaf(av.y, bv.w, acc[1][3]);
            acc[2][0] = fmaf(av.z, bv.x, acc[2][0]);
            acc[2][1] = fmaf(av.z, bv.y, acc[2][1]);
            acc[2][2] = fmaf(av.z, bv.z, acc[2][2]);
            acc[2][3] = fmaf(av.z, bv.w, acc[2][3]);
            acc[3][0] = fmaf(av.w, bv.x, acc[3][0]);
            acc[3][1] = fmaf(av.w, bv.y, acc[3][1]);
            acc[3][2] = fmaf(av.w, bv.z, acc[3][2]);
            acc[3][3] = fmaf(av.w, bv.w, acc[3][3]);
        }
    }

    float4 badd = make_float4(0.f, 0.f, 0.f, 0.f);
    if (bias) badd = *(const float4*)&bias[bn + tn];
#pragma unroll
    for (int i = 0; i < 4; i++) {
        float4 r = make_float4(acc[i][0] + badd.x, acc[i][1] + badd.y,
                               acc[i][2] + badd.z, acc[i][3] + badd.w);
        *(float4*)&C[(size_t)(bm + tm + i) * N + bn + tn] = r;
    }
}

// =================================================================
// Mask resize (64x64 -> 32x32 nearest, flattened to m[1024]) + count
// 1 block, 1024 threads
// =================================================================
__global__ void resize_mask(const float* __restrict__ mask,
                            float* __restrict__ m, float* __restrict__ cnt)
{
    int i = threadIdx.x;
    int r = i >> 5, c = i & 31;
    float mv = mask[(r * 2) * 64 + c * 2];
    m[i] = mv;
    __shared__ float red[1024];
    red[i] = mv;
    __syncthreads();
    for (int s = 512; s > 0; s >>= 1) {
        if (i < s) red[i] += red[i + s];
        __syncthreads();
    }
    if (i == 0) cnt[0] = red[0];
}

// =================================================================
// AdaIN per-channel stats -> scale/shift. 1024 blocks (2 tensors x 512 ch)
// =================================================================
__global__ __launch_bounds__(256) void adain_stats(
    const float* __restrict__ kbuf, const float* __restrict__ vbuf,
    const float* __restrict__ m, const float* __restrict__ cntp,
    float* __restrict__ scaleArr, float* __restrict__ shiftArr)
{
    int tensor = blockIdx.x >> 9;
    int ch     = blockIdx.x & 511;
    const float* T    = tensor ? vbuf : kbuf;
    const float* ref  = T + ch;                 // batch 0
    const float* feat = T + (size_t)N_ * QD_ + ch;  // batch 1

    float rs = 0.f, rss = 0.f, fs = 0.f, fss = 0.f;
    for (int i = threadIdx.x; i < N_; i += 256) {
        float rv = ref [(size_t)i * QD_];
        float fv = feat[(size_t)i * QD_];
        float mv = m[i];
        rs  += rv;        rss += rv * rv;
        fs  += mv * fv;   fss += mv * fv * fv;
    }
    __shared__ float4 red[256];
    red[threadIdx.x] = make_float4(rs, rss, fs, fss);
    __syncthreads();
    for (int s = 128; s > 0; s >>= 1) {
        if (threadIdx.x < s) {
            float4 a = red[threadIdx.x], b = red[threadIdx.x + s];
            red[threadIdx.x] = make_float4(a.x + b.x, a.y + b.y, a.z + b.z, a.w + b.w);
        }
        __syncthreads();
    }
    if (threadIdx.x == 0) {
        float cnt = cntp[0];
        float4 r  = red[0];
        float ref_mean = r.x * (1.0f / N_);
        float ref_var  = (r.y - (float)N_ * ref_mean * ref_mean) * (1.0f / (N_ - 1));
        float ref_std  = sqrtf(fmaxf(ref_var, 0.f));
        float f_mean   = r.z / cnt;
        float f_var    = (r.w - cnt * f_mean * f_mean) / (cnt - 1.0f);
        float f_std    = sqrtf(fmaxf(f_var, 0.f));
        float sc       = ref_std / f_std;
        scaleArr[blockIdx.x] = sc;
        shiftArr[blockIdx.x] = ref_mean - f_mean * sc;
    }
}

// =================================================================
// AdaIN apply (in-place on batch-1 rows where m==1).
// grid 2048 blocks (tensor*1024 + row), 512 threads = channels
// =================================================================
__global__ void adain_apply(float* __restrict__ kbuf, float* __restrict__ vbuf,
                            const float* __restrict__ m,
                            const float* __restrict__ scaleArr,
                            const float* __restrict__ shiftArr)
{
    int row    = blockIdx.x & 1023;
    int tensor = blockIdx.x >> 10;
    if (m[row] < 0.5f) return;
    float* T = tensor ? vbuf : kbuf;
    int ch   = threadIdx.x;
    float sc = scaleArr[tensor * QD_ + ch];
    float sh = shiftArr[tensor * QD_ + ch];
    size_t off = (size_t)(N_ + row) * QD_ + ch;
    T[off] = fmaf(T[off], sc, sh);
}

// =================================================================
// Flash attention fp32. grid (16 qtiles, 16 bh), 64 threads (1 query each).
// Keys 0..1023 = own batch (post-adain), 1024..2047 = batch-0 (ref) rows.
// Batch-1 queries with m==0 get -1e9 on the second half.
// =================================================================
#define ATTN_SMEM_FLOATS (64*68 + 64*68 + 64*64)
__global__ __launch_bounds__(64) void attn_kernel(
    const float* __restrict__ q, const float* __restrict__ k,
    const float* __restrict__ v, const float* __restrict__ m,
    float* __restrict__ out)
{
    extern __shared__ float sm[];
    float* ks = sm;                 // [64][68]
    float* vs = sm + 64 * 68;       // [64][68]
    float* ss = sm + 2 * 64 * 68;   // [64][64]  s/p matrix, ss[j*64+t]

    const int t  = threadIdx.x;
    const int bh = blockIdx.y;
    const int b  = bh >> 3;
    const int h  = bh & 7;
    const int q0 = blockIdx.x * 64;

    // ---- stage q tile through smem, then into registers ----
    const float* qbase = q + (size_t)(b * N_ + q0) * QD_ + h * DH_;
    for (int idx = t; idx < 64 * 16; idx += 64) {
        int row = idx >> 4, c4 = idx & 15;
        ((float4*)(ks + row * 68))[c4] = ((const float4*)(qbase + (size_t)row * QD_))[c4];
    }
    __syncthreads();
    float qreg[64];
#pragma unroll
    for (int d4 = 0; d4 < 16; d4++) {
        float4 qq = ((const float4*)(ks + t * 68))[d4];
        qreg[4*d4+0] = qq.x; qreg[4*d4+1] = qq.y;
        qreg[4*d4+2] = qq.z; qreg[4*d4+3] = qq.w;
    }

    float o[64];
#pragma unroll
    for (int d = 0; d < 64; d++) o[d] = 0.f;
    float ml = -1e30f, l = 0.f;

    float maskadd = 0.f;
    if (b == 1 && m[q0 + t] < 0.5f) maskadd = -1e9f;

    for (int kt = 0; kt < 32; kt++) {
        const int j0 = kt * 64;
        const float *kb, *vb;
        if (j0 < N_) {
            kb = k + (size_t)(b * N_ + j0) * QD_ + h * DH_;
            vb = v + (size_t)(b * N_ + j0) * QD_ + h * DH_;
        } else {
            kb = k + (size_t)(j0 - N_) * QD_ + h * DH_;   // batch 0 (ref)
            vb = v + (size_t)(j0 - N_) * QD_ + h * DH_;
        }
        __syncthreads();   // protect previous tile reads
        for (int idx = t; idx < 64 * 16; idx += 64) {
            int row = idx >> 4, c4 = idx & 15;
            ((float4*)(ks + row * 68))[c4] = ((const float4*)(kb + (size_t)row * QD_))[c4];
            ((float4*)(vs + row * 68))[c4] = ((const float4*)(vb + (size_t)row * QD_))[c4];
        }
        __syncthreads();

        const float addj = (kt >= 16) ? maskadd : 0.f;
        float tmax = -1e30f;
#pragma unroll 1
        for (int j = 0; j < 64; j++) {
            const float4* kr = (const float4*)(ks + j * 68);
            float a0 = 0.f, a1 = 0.f, a2 = 0.f, a3 = 0.f;
#pragma unroll
            for (int d4 = 0; d4 < 16; d4++) {
                float4 kk = kr[d4];
                a0 = fmaf(qreg[4*d4+0], kk.x, a0);
                a1 = fmaf(qreg[4*d4+1], kk.y, a1);
                a2 = fmaf(qreg[4*d4+2], kk.z, a2);
                a3 = fmaf(qreg[4*d4+3], kk.w, a3);
            }
            float s = ((a0 + a1) + (a2 + a3)) * SCALE_ + addj;
            ss[j * 64 + t] = s;
            tmax = fmaxf(tmax, s);
        }

        float mnew = fmaxf(ml, tmax);
        float corr = __expf(ml - mnew);
        l *= corr;
#pragma unroll
        for (int d = 0; d < 64; d++) o[d] *= corr;

#pragma unroll 1
        for (int j = 0; j < 64; j++) {
            float p = __expf(ss[j * 64 + t] - mnew);
            l += p;
            const float4* vr = (const float4*)(vs + j * 68);
#pragma unroll
            for (int d4 = 0; d4 < 16; d4++) {
                float4 vv = vr[d4];
                o[4*d4+0] = fmaf(p, vv.x, o[4*d4+0]);
                o[4*d4+1] = fmaf(p, vv.y, o[4*d4+1]);
                o[4*d4+2] = fmaf(p, vv.z, o[4*d4+2]);
                o[4*d4+3] = fmaf(p, vv.w, o[4*d4+3]);
            }
        }
        ml = mnew;
    }

    const float inv = 1.0f / l;
    float* ob = out + (size_t)(b * N_ + q0 + t) * QD_ + h * DH_;
#pragma unroll
    for (int d4 = 0; d4 < 16; d4++) {
        ((float4*)ob)[d4] = make_float4(o[4*d4+0] * inv, o[4*d4+1] * inv,
                                        o[4*d4+2] * inv, o[4*d4+3] * inv);
    }
}

// =================================================================
extern "C" void kernel_launch(void* const* d_in, const int* in_sizes, int n_in,
                              void* d_out, int out_size)
{
    const float* x    = (const float*)d_in[0];
    const float* mask = (const float*)d_in[1];
    const float* Wq   = (const float*)d_in[2];
    const float* Wk   = (const float*)d_in[3];
    const float* Wv   = (const float*)d_in[4];
    const float* Wo   = (const float*)d_in[5];
    const float* bo   = (const float*)d_in[6];
    // d_in[7] = share (unused)

    float *q, *k, *v, *ao, *m, *cnt, *sc, *sh;
    cudaGetSymbolAddress((void**)&q,   g_q);
    cudaGetSymbolAddress((void**)&k,   g_k);
    cudaGetSymbolAddress((void**)&v,   g_v);
    cudaGetSymbolAddress((void**)&ao,  g_ao);
    cudaGetSymbolAddress((void**)&m,   g_m);
    cudaGetSymbolAddress((void**)&cnt, g_cnt);
    cudaGetSymbolAddress((void**)&sc,  g_scale);
    cudaGetSymbolAddress((void**)&sh,  g_shift);

    const int M = B_ * N_;   // 2048
    dim3 gproj(QD_ / 64, M / 64);   // (8, 32)

    gemm_nt<<<gproj, 256>>>(x, Wq, nullptr, q, M, QD_, QD_);
    gemm_nt<<<gproj, 256>>>(x, Wk, nullptr, k, M, QD_, QD_);
    gemm_nt<<<gproj, 256>>>(x, Wv, nullptr, v, M, QD_, QD_);

    resize_mask<<<1, 1024>>>(mask, m, cnt);
    adain_stats<<<1024, 256>>>(k, v, m, cnt, sc, sh);
    adain_apply<<<2048, 512>>>(k, v, m, sc, sh);

    const int smem_bytes = ATTN_SMEM_FLOATS * sizeof(float);   // 51200
    cudaFuncSetAttribute(attn_kernel, cudaFuncAttributeMaxDynamicSharedMemorySize, smem_bytes);
    attn_kernel<<<dim3(16, 16), 64, smem_bytes>>>(q, k, v, m, ao);

    gemm_nt<<<gproj, 256>>>(ao, Wo, bo, (float*)d_out, M, QD_, QD_);
}

// round 2
// speedup vs baseline: 1.0141x; 1.0141x over previous
#include <cuda_runtime.h>
#include <math.h>

// Problem constants
#define B_    2
#define N_    1024
#define QD_   512
#define H_    8
#define DH_   64
#define SCALE_ 0.125f   // DH^-0.5

typedef unsigned long long ull;

// ---------------- packed fp32x2 helpers (Blackwell) ----------------
__device__ __forceinline__ ull pk2(float lo, float hi) {
    ull r;
    asm("mov.b64 %0, {%1,%2};" : "=l"(r) : "f"(lo), "f"(hi));
    return r;
}
__device__ __forceinline__ void upk2(ull v, float& lo, float& hi) {
    asm("mov.b64 {%0,%1}, %2;" : "=f"(lo), "=f"(hi) : "l"(v));
}
__device__ __forceinline__ void fma2(ull& acc, ull a, ull b) {
    asm("fma.rn.f32x2 %0, %1, %2, %0;" : "+l"(acc) : "l"(a), "l"(b));
}
__device__ __forceinline__ ull add2(ull a, ull b) {
    ull d; asm("add.rn.f32x2 %0, %1, %2;" : "=l"(d) : "l"(a), "l"(b)); return d;
}
__device__ __forceinline__ ull mul2(ull a, ull b) {
    ull d; asm("mul.rn.f32x2 %0, %1, %2;" : "=l"(d) : "l"(a), "l"(b)); return d;
}

// ---------------- scratch (no allocation allowed) ----------------
__device__ float g_q [B_*N_*QD_];
__device__ float g_k [B_*N_*QD_];
__device__ float g_v [B_*N_*QD_];
__device__ float g_ao[B_*N_*QD_];
__device__ float g_m [N_];
__device__ float g_cnt[1];
__device__ float g_scale[2*QD_];
__device__ float g_shift[2*QD_];

// =================================================================
// GEMM: C[M,N] = A[M,K] * B[N,K]^T (+ bias[N])
// 256 threads, 128x64 tile, 8x4 microtile, packed f32x2 math,
// register prefetch across k-steps.
// =================================================================
__global__ __launch_bounds__(256) void gemm_nt(
    const float* __restrict__ A, const float* __restrict__ Bm,
    const float* __restrict__ bias, float* __restrict__ C,
    int M, int N, int K)
{
    __shared__ float As[16][132];
    __shared__ float Bs[16][68];
    const int tid = threadIdx.x;
    const int bm  = blockIdx.y * 128;
    const int bn  = blockIdx.x * 64;
    const int tm  = (tid & 15) * 8;
    const int tn  = (tid >> 4) * 4;

    // load indices
    const int arow = tid >> 1;          // 0..127
    const int akc  = (tid & 1) * 8;     // k offset 0 or 8
    const int brow = tid >> 2;          // 0..63
    const int bkc  = (tid & 3) * 4;     // k offset 0,4,8,12

    ull acc[4][4];
#pragma unroll
    for (int i = 0; i < 4; i++)
#pragma unroll
        for (int j = 0; j < 4; j++) acc[i][j] = 0ull;

    const float4* Ap = (const float4*)(A  + (size_t)(bm + arow) * K + akc);
    const float4* Bp = (const float4*)(Bm + (size_t)(bn + brow) * K + bkc);

    // prefetch k0 = 0
    float4 pa0 = Ap[0];
    float4 pa1 = Ap[1];
    float4 pb0 = Bp[0];

    const int ksteps = K >> 4;
    for (int ks = 0; ks < ksteps; ks++) {
        __syncthreads();
        // store staged fragments
        As[akc+0][arow] = pa0.x; As[akc+1][arow] = pa0.y;
        As[akc+2][arow] = pa0.z; As[akc+3][arow] = pa0.w;
        As[akc+4][arow] = pa1.x; As[akc+5][arow] = pa1.y;
        As[akc+6][arow] = pa1.z; As[akc+7][arow] = pa1.w;
        Bs[bkc+0][brow] = pb0.x; Bs[bkc+1][brow] = pb0.y;
        Bs[bkc+2][brow] = pb0.z; Bs[bkc+3][brow] = pb0.w;
        __syncthreads();

        // prefetch next k-step
        if (ks + 1 < ksteps) {
            int off = (ks + 1) * 4;   // in float4 units
            pa0 = Ap[off];
            pa1 = Ap[off + 1];
            pb0 = Bp[off];
        }

#pragma unroll
        for (int kk = 0; kk < 16; kk++) {
            float4 av0 = *(const float4*)&As[kk][tm];
            float4 av1 = *(const float4*)&As[kk][tm + 4];
            float4 bv  = *(const float4*)&Bs[kk][tn];
            ull a01 = pk2(av0.x, av0.y);
            ull a23 = pk2(av0.z, av0.w);
            ull a45 = pk2(av1.x, av1.y);
            ull a67 = pk2(av1.z, av1.w);
            ull b0 = pk2(bv.x, bv.x);
            ull b1 = pk2(bv.y, bv.y);
            ull b2 = pk2(bv.z, bv.z);
            ull b3 = pk2(bv.w, bv.w);
            fma2(acc[0][0], a01, b0); fma2(acc[0][1], a01, b1);
            fma2(acc[0][2], a01, b2); fma2(acc[0][3], a01, b3);
            fma2(acc[1][0], a23, b0); fma2(acc[1][1], a23, b1);
            fma2(acc[1][2], a23, b2); fma2(acc[1][3], a23, b3);
            fma2(acc[2][0], a45, b0); fma2(acc[2][1], a45, b1);
            fma2(acc[2][2], a45, b2); fma2(acc[2][3], a45, b3);
            fma2(acc[3][0], a67, b0); fma2(acc[3][1], a67, b1);
            fma2(acc[3][2], a67, b2); fma2(acc[3][3], a67, b3);
        }
    }

    float4 badd = make_float4(0.f, 0.f, 0.f, 0.f);
    if (bias) badd = *(const float4*)&bias[bn + tn];
#pragma unroll
    for (int i2 = 0; i2 < 4; i2++) {
        float lo[4], hi[4];
#pragma unroll
        for (int j = 0; j < 4; j++) upk2(acc[i2][j], lo[j], hi[j]);
        float4 r0 = make_float4(lo[0]+badd.x, lo[1]+badd.y, lo[2]+badd.z, lo[3]+badd.w);
        float4 r1 = make_float4(hi[0]+badd.x, hi[1]+badd.y, hi[2]+badd.z, hi[3]+badd.w);
        *(float4*)&C[(size_t)(bm + tm + 2*i2    ) * N + bn + tn] = r0;
        *(float4*)&C[(size_t)(bm + tm + 2*i2 + 1) * N + bn + tn] = r1;
    }
}

// =================================================================
// Mask resize (64x64 -> 32x32 nearest, flattened to m[1024]) + count
// =================================================================
__global__ void resize_mask(const float* __restrict__ mask,
                            float* __restrict__ m, float* __restrict__ cnt)
{
    int i = threadIdx.x;
    int r = i >> 5, c = i & 31;
    float mv = mask[(r * 2) * 64 + c * 2];
    m[i] = mv;
    __shared__ float red[1024];
    red[i] = mv;
    __syncthreads();
    for (int s = 512; s > 0; s >>= 1) {
        if (i < s) red[i] += red[i + s];
        __syncthreads();
    }
    if (i == 0) cnt[0] = red[0];
}

// =================================================================
// AdaIN per-channel stats -> scale/shift. 1024 blocks (2 tensors x 512 ch)
// =================================================================
__global__ __launch_bounds__(256) void adain_stats(
    const float* __restrict__ kbuf, const float* __restrict__ vbuf,
    const float* __restrict__ m, const float* __restrict__ cntp,
    float* __restrict__ scaleArr, float* __restrict__ shiftArr)
{
    int tensor = blockIdx.x >> 9;
    int ch     = blockIdx.x & 511;
    const float* T    = tensor ? vbuf : kbuf;
    const float* ref  = T + ch;                     // batch 0
    const float* feat = T + (size_t)N_ * QD_ + ch;  // batch 1

    float rs = 0.f, rss = 0.f, fs = 0.f, fss = 0.f;
    for (int i = threadIdx.x; i < N_; i += 256) {
        float rv = ref [(size_t)i * QD_];
        float fv = feat[(size_t)i * QD_];
        float mv = m[i];
        rs  += rv;        rss += rv * rv;
        fs  += mv * fv;   fss += mv * fv * fv;
    }
    __shared__ float4 red[256];
    red[threadIdx.x] = make_float4(rs, rss, fs, fss);
    __syncthreads();
    for (int s = 128; s > 0; s >>= 1) {
        if (threadIdx.x < s) {
            float4 a = red[threadIdx.x], b = red[threadIdx.x + s];
            red[threadIdx.x] = make_float4(a.x + b.x, a.y + b.y, a.z + b.z, a.w + b.w);
        }
        __syncthreads();
    }
    if (threadIdx.x == 0) {
        float cnt = cntp[0];
        float4 r  = red[0];
        float ref_mean = r.x * (1.0f / N_);
        float ref_var  = (r.y - (float)N_ * ref_mean * ref_mean) * (1.0f / (N_ - 1));
        float ref_std  = sqrtf(fmaxf(ref_var, 0.f));
        float f_mean   = r.z / cnt;
        float f_var    = (r.w - cnt * f_mean * f_mean) / (cnt - 1.0f);
        float f_std    = sqrtf(fmaxf(f_var, 0.f));
        float sc       = ref_std / f_std;
        scaleArr[blockIdx.x] = sc;
        shiftArr[blockIdx.x] = ref_mean - f_mean * sc;
    }
}

// =================================================================
// AdaIN apply (in-place on batch-1 rows where m==1).
// =================================================================
__global__ void adain_apply(float* __restrict__ kbuf, float* __restrict__ vbuf,
                            const float* __restrict__ m,
                            const float* __restrict__ scaleArr,
                            const float* __restrict__ shiftArr)
{
    int row    = blockIdx.x & 1023;
    int tensor = blockIdx.x >> 10;
    if (m[row] < 0.5f) return;
    float* T = tensor ? vbuf : kbuf;
    int ch   = threadIdx.x;
    float sc = scaleArr[tensor * QD_ + ch];
    float sh = shiftArr[tensor * QD_ + ch];
    size_t off = (size_t)(N_ + row) * QD_ + ch;
    T[off] = fmaf(T[off], sc, sh);
}

// =================================================================
// Flash attention fp32 with packed f32x2 math + warp specialization.
// Block: 128 threads. Threads 0-63 = consumers (1 query each),
// threads 64-127 = producers (fill K/V double buffers).
// grid (16 qtiles, 16 bh). Keys 0..1023 = own batch (post-adain),
// 1024..2047 = batch-0 (ref) rows.
// =================================================================
#define KS0_ 0
#define KS1_ 4352
#define VS0_ 8704
#define VS1_ 13056
#define SS_  17408
#define ATTN_SMEM_FLOATS (17408 + 64*64)

__global__ __launch_bounds__(128) void attn_kernel(
    const float* __restrict__ q, const float* __restrict__ k,
    const float* __restrict__ v, const float* __restrict__ m,
    float* __restrict__ out)
{
    extern __shared__ float sm[];
    float* ss = sm + SS_;

    const int tid = threadIdx.x;
    const bool consumer = tid < 64;
    const int t  = tid & 63;
    const int bh = blockIdx.y;
    const int b  = bh >> 3;
    const int h  = bh & 7;
    const int q0 = blockIdx.x * 64;

    // ---- producers stage q tile into ks0 buffer ----
    const float* qbase = q + (size_t)(b * N_ + q0) * QD_ + h * DH_;
    if (!consumer) {
        for (int idx = t; idx < 64 * 16; idx += 64) {
            int row = idx >> 4, c4 = idx & 15;
            ((float4*)(sm + KS0_ + row * 68))[c4] =
                ((const float4*)(qbase + (size_t)row * QD_))[c4];
        }
    }
    __syncthreads();

    ull qp[32];
    if (consumer) {
#pragma unroll
        for (int d4 = 0; d4 < 16; d4++) {
            float4 qq = ((const float4*)(sm + KS0_ + t * 68))[d4];
            qp[2*d4]   = pk2(qq.x, qq.y);
            qp[2*d4+1] = pk2(qq.z, qq.w);
        }
    }
    __syncthreads();

    // ---- producers load tile 0 into buffer 0 ----
    if (!consumer) {
        const float* kb = k + (size_t)(b * N_) * QD_ + h * DH_;
        const float* vb = v + (size_t)(b * N_) * QD_ + h * DH_;
        for (int idx = t; idx < 64 * 16; idx += 64) {
            int row = idx >> 4, c4 = idx & 15;
            ((float4*)(sm + KS0_ + row * 68))[c4] = ((const float4*)(kb + (size_t)row * QD_))[c4];
            ((float4*)(sm + VS0_ + row * 68))[c4] = ((const float4*)(vb + (size_t)row * QD_))[c4];
        }
    }
    __syncthreads();

    ull o2[32];
#pragma unroll
    for (int i = 0; i < 32; i++) o2[i] = 0ull;
    float ml = -1e30f, l = 0.f;

    float maskadd = 0.f;
    if (consumer && b == 1 && m[q0 + t] < 0.5f) maskadd = -1e9f;

    for (int kt = 0; kt < 32; kt++) {
        const int cur = kt & 1;

        if (!consumer && kt < 31) {
            // produce tile kt+1 into the other buffer
            const int j0 = (kt + 1) * 64;
            const float *kb, *vb;
            if (j0 < N_) {
                kb = k + (size_t)(b * N_ + j0) * QD_ + h * DH_;
                vb = v + (size_t)(b * N_ + j0) * QD_ + h * DH_;
            } else {
                kb = k + (size_t)(j0 - N_) * QD_ + h * DH_;   // batch 0 (ref)
                vb = v + (size_t)(j0 - N_) * QD_ + h * DH_;
            }
            float* kd = sm + (cur ? KS0_ : KS1_);
            float* vd = sm + (cur ? VS0_ : VS1_);
            for (int idx = t; idx < 64 * 16; idx += 64) {
                int row = idx >> 4, c4 = idx & 15;
                ((float4*)(kd + row * 68))[c4] = ((const float4*)(kb + (size_t)row * QD_))[c4];
                ((float4*)(vd + row * 68))[c4] = ((const float4*)(vb + (size_t)row * QD_))[c4];
            }
        }

        if (consumer) {
            const float* ksb = sm + (cur ? KS1_ : KS0_);
            const float* vsb = sm + (cur ? VS1_ : VS0_);
            const float addj = (kt >= 16) ? maskadd : 0.f;

            float tmax = -1e30f;
#pragma unroll 1
            for (int j = 0; j < 64; j++) {
                const float4* kr = (const float4*)(ksb + j * 68);
                ull a0 = 0ull, a1 = 0ull, a2 = 0ull, a3 = 0ull;
#pragma unroll
                for (int d4 = 0; d4 < 16; d4 += 2) {
                    float4 ka = kr[d4];
                    float4 kb4 = kr[d4 + 1];
                    fma2(a0, qp[2*d4],   pk2(ka.x,  ka.y));
                    fma2(a1, qp[2*d4+1], pk2(ka.z,  ka.w));
                    fma2(a2, qp[2*d4+2], pk2(kb4.x, kb4.y));
                    fma2(a3, qp[2*d4+3], pk2(kb4.z, kb4.w));
                }
                ull u = add2(a0, a2);
                ull w = add2(a1, a3);
                ull z = add2(u, w);
                float zl, zh; upk2(z, zl, zh);
                float s = (zl + zh) * SCALE_ + addj;
                ss[j * 64 + t] = s;
                tmax = fmaxf(tmax, s);
            }

            float mnew = fmaxf(ml, tmax);
            float corr = __expf(ml - mnew);
            l *= corr;
            ull cc = pk2(corr, corr);
#pragma unroll
            for (int i = 0; i < 32; i++) o2[i] = mul2(o2[i], cc);

#pragma unroll 1
            for (int j = 0; j < 64; j++) {
                float p = __expf(ss[j * 64 + t] - mnew);
                l += p;
                ull pp = pk2(p, p);
                const float4* vr = (const float4*)(vsb + j * 68);
#pragma unroll
                for (int d4 = 0; d4 < 16; d4++) {
                    float4 vv = vr[d4];
                    fma2(o2[2*d4],   pp, pk2(vv.x, vv.y));
                    fma2(o2[2*d4+1], pp, pk2(vv.z, vv.w));
                }
            }
            ml = mnew;
        }
        __syncthreads();
    }

    if (consumer) {
        const float inv = 1.0f / l;
        float* ob = out + (size_t)(b * N_ + q0 + t) * QD_ + h * DH_;
#pragma unroll
        for (int d4 = 0; d4 < 16; d4++) {
            float l0, h0, l1, h1;
            upk2(o2[2*d4],   l0, h0);
            upk2(o2[2*d4+1], l1, h1);
            ((float4*)ob)[d4] = make_float4(l0 * inv, h0 * inv, l1 * inv, h1 * inv);
        }
    }
}

// =================================================================
extern "C" void kernel_launch(void* const* d_in, const int* in_sizes, int n_in,
                              void* d_out, int out_size)
{
    const float* x    = (const float*)d_in[0];
    const float* mask = (const float*)d_in[1];
    const float* Wq   = (const float*)d_in[2];
    const float* Wk   = (const float*)d_in[3];
    const float* Wv   = (const float*)d_in[4];
    const float* Wo   = (const float*)d_in[5];
    const float* bo   = (const float*)d_in[6];
    // d_in[7] = share (unused)

    float *q, *k, *v, *ao, *m, *cnt, *sc, *sh;
    cudaGetSymbolAddress((void**)&q,   g_q);
    cudaGetSymbolAddress((void**)&k,   g_k);
    cudaGetSymbolAddress((void**)&v,   g_v);
    cudaGetSymbolAddress((void**)&ao,  g_ao);
    cudaGetSymbolAddress((void**)&m,   g_m);
    cudaGetSymbolAddress((void**)&cnt, g_cnt);
    cudaGetSymbolAddress((void**)&sc,  g_scale);
    cudaGetSymbolAddress((void**)&sh,  g_shift);

    const int M = B_ * N_;            // 2048
    dim3 gproj(QD_ / 64, M / 128);    // (8, 16)

    gemm_nt<<<gproj, 256>>>(x, Wq, nullptr, q, M, QD_, QD_);
    gemm_nt<<<gproj, 256>>>(x, Wk, nullptr, k, M, QD_, QD_);
    gemm_nt<<<gproj, 256>>>(x, Wv, nullptr, v, M, QD_, QD_);

    resize_mask<<<1, 1024>>>(mask, m, cnt);
    adain_stats<<<1024, 256>>>(k, v, m, cnt, sc, sh);
    adain_apply<<<2048, 512>>>(k, v, m, sc, sh);

    const int smem_bytes = ATTN_SMEM_FLOATS * sizeof(float);   // 86016
    cudaFuncSetAttribute(attn_kernel, cudaFuncAttributeMaxDynamicSharedMemorySize, smem_bytes);
    attn_kernel<<<dim3(16, 16), 128, smem_bytes>>>(q, k, v, m, ao);

    gemm_nt<<<gproj, 256>>>(ao, Wo, bo, (float*)d_out, M, QD_, QD_);
}

// round 4
// speedup vs baseline: 3.5267x; 3.4776x over previous
#include <cuda_runtime.h>
#include <cuda_bf16.h>
#include <math.h>
#include <stdint.h>

// Problem constants
#define B_    2
#define N_    1024
#define QD_   512
#define H_    8
#define DH_   64
#define SCALE_ 0.125f   // DH^-0.5
#define KVSPLIT 2

// ---------------- PTX helpers ----------------
__device__ __forceinline__ uint32_t smem_u32(const void* p) {
    uint32_t a;
    asm("{ .reg .u64 t; cvta.to.shared.u64 t, %1; cvt.u32.u64 %0, t; }" : "=r"(a) : "l"(p));
    return a;
}
__device__ __forceinline__ void cp16(uint32_t dst, const void* src) {
    asm volatile("cp.async.cg.shared.global [%0], [%1], 16;" :: "r"(dst), "l"(src) : "memory");
}
#define CP_COMMIT asm volatile("cp.async.commit_group;" ::: "memory")
#define CP_WAIT1  asm volatile("cp.async.wait_group 1;" ::: "memory")
#define CP_WAIT0  asm volatile("cp.async.wait_group 0;" ::: "memory")

__device__ __forceinline__ void ldsm4(uint32_t* r, uint32_t a) {
    asm volatile("ldmatrix.sync.aligned.m8n8.x4.shared.b16 {%0,%1,%2,%3}, [%4];"
                 : "=r"(r[0]), "=r"(r[1]), "=r"(r[2]), "=r"(r[3]) : "r"(a));
}
__device__ __forceinline__ void ldsm4t(uint32_t* r, uint32_t a) {
    asm volatile("ldmatrix.sync.aligned.m8n8.x4.trans.shared.b16 {%0,%1,%2,%3}, [%4];"
                 : "=r"(r[0]), "=r"(r[1]), "=r"(r[2]), "=r"(r[3]) : "r"(a));
}
__device__ __forceinline__ void mma16816(float* c, const uint32_t* a, uint32_t b0, uint32_t b1) {
    asm volatile(
        "mma.sync.aligned.m16n8k16.row.col.f32.bf16.bf16.f32 "
        "{%0,%1,%2,%3}, {%4,%5,%6,%7}, {%8,%9}, {%0,%1,%2,%3};"
        : "+f"(c[0]), "+f"(c[1]), "+f"(c[2]), "+f"(c[3])
        : "r"(a[0]), "r"(a[1]), "r"(a[2]), "r"(a[3]), "r"(b0), "r"(b1));
}
__device__ __forceinline__ uint32_t pkbf(float lo, float hi) {
    uint32_t r;
    asm("cvt.rn.satfinite.bf16x2.f32 %0, %1, %2;" : "=r"(r) : "f"(hi), "f"(lo));
    return r;
}
__device__ __forceinline__ float lo16f(uint32_t u) { return __uint_as_float(u << 16); }
__device__ __forceinline__ float hi16f(uint32_t u) { return __uint_as_float(u & 0xffff0000u); }

// ---------------- scratch ----------------
__device__ float g_q [B_*N_*QD_];
__device__ float g_k [B_*N_*QD_];
__device__ float g_v [B_*N_*QD_];
__device__ float g_ao[B_*N_*QD_];
__device__ float g_m [N_];
__device__ float g_cnt[1];
__device__ float g_scale[2*QD_];
__device__ float g_shift[2*QD_];
__device__ __nv_bfloat16 g_xhi[B_*N_*QD_], g_xlo[B_*N_*QD_];
__device__ __nv_bfloat16 g_whi[4][QD_*QD_], g_wlo[4][QD_*QD_];
__device__ __nv_bfloat16 g_qhi[B_*N_*QD_], g_qlo[B_*N_*QD_];
__device__ __nv_bfloat16 g_khi[B_*N_*QD_], g_klo[B_*N_*QD_];
__device__ __nv_bfloat16 g_vhi[B_*N_*QD_], g_vlo[B_*N_*QD_];
__device__ __nv_bfloat16 g_aohi[B_*N_*QD_], g_aolo[B_*N_*QD_];
__device__ float g_part[KVSPLIT*16*N_*DH_];
__device__ float g_lsum[KVSPLIT*16*N_];

// =================================================================
// fp32 -> bf16 hi/lo split
// =================================================================
__global__ __launch_bounds__(256) void cvt_split(
    const float* __restrict__ x, __nv_bfloat16* __restrict__ hi,
    __nv_bfloat16* __restrict__ lo, int n)
{
    int i = blockIdx.x * 256 + threadIdx.x;
    if (i < n) {
        float v = x[i];
        __nv_bfloat16 h = __float2bfloat16(v);
        hi[i] = h;
        lo[i] = __float2bfloat16(v - __bfloat162float(h));
    }
}

// =================================================================
// mma.sync GEMM: C[M,N] = (Ahi+Alo)(Bhi+Blo)^T (+bias)
// 256 thr (8 warps), tile 128x64, BK=32, double-buffered cp.async,
// split-bf16 (3 mma products). smem row stride 80B (conflict-free).
// =================================================================
#define G_AH(s) ((s)*30720 + 0)
#define G_AL(s) ((s)*30720 + 10240)
#define G_BH(s) ((s)*30720 + 20480)
#define G_BL(s) ((s)*30720 + 25600)
#define GEMM_SMEM 61440

__global__ __launch_bounds__(256) void gemm_mma(
    const __nv_bfloat16* __restrict__ Ahi, const __nv_bfloat16* __restrict__ Alo,
    const __nv_bfloat16* __restrict__ Bhi, const __nv_bfloat16* __restrict__ Blo,
    const float* __restrict__ bias, float* __restrict__ C,
    int M, int N, int K)
{
    extern __shared__ __align__(16) char sg[];
    const uint32_t sb = smem_u32(sg);
    const int tid = threadIdx.x;
    const int warp = tid >> 5, lane = tid & 31;
    const int wm = warp & 3, wn = warp >> 2;
    const int bm = blockIdx.y * 128, bn = blockIdx.x * 64;
    const int grp = lane >> 3, lr = lane & 7;

    auto load_stage = [&](int s, int k0) {
#pragma unroll
        for (int i = 0; i < 4; i++) {
            int c = tid + i * 256;
            int p = c >> 9, r = (c >> 2) & 127, col = c & 3;
            const __nv_bfloat16* src = (p ? Alo : Ahi) + (size_t)(bm + r) * K + k0 + col * 8;
            cp16(sb + (p ? G_AL(s) : G_AH(s)) + r * 80 + col * 16, src);
        }
#pragma unroll
        for (int i = 0; i < 2; i++) {
            int c = tid + i * 256;
            int p = c >> 8, r = (c >> 2) & 63, col = c & 3;
            const __nv_bfloat16* src = (p ? Blo : Bhi) + (size_t)(bn + r) * K + k0 + col * 8;
            cp16(sb + (p ? G_BL(s) : G_BH(s)) + r * 80 + col * 16, src);
        }
    };

    float acc[32];
#pragma unroll
    for (int i = 0; i < 32; i++) acc[i] = 0.f;

    const int ksteps = K >> 5;   // 16
    load_stage(0, 0);  CP_COMMIT;
    load_stage(1, 32); CP_COMMIT;

    const uint32_t aaddr = (wm * 32 + (lane & 15)) * 80 + (lane >> 4) * 16;
    const int rowB = wn * 32 + ((grp >> 1) << 3) + lr;
    const int colB = (grp & 1) * 16;

    for (int kt = 0; kt < ksteps; kt++) {
        if (kt == ksteps - 1) { CP_WAIT0; } else { CP_WAIT1; }
        __syncthreads();
        const int s = kt & 1;
        const uint32_t ahb = sb + G_AH(s), alb = sb + G_AL(s);
        const uint32_t bhb = sb + G_BH(s), blb = sb + G_BL(s);

#pragma unroll
        for (int kb = 0; kb < 2; kb++) {
            uint32_t ah[2][4], al[2][4];
#pragma unroll
            for (int mt = 0; mt < 2; mt++) {
                ldsm4(ah[mt], ahb + aaddr + mt * 16 * 80 + kb * 32);
                ldsm4(al[mt], alb + aaddr + mt * 16 * 80 + kb * 32);
            }
#pragma unroll
            for (int p = 0; p < 2; p++) {
                uint32_t bhf[4], blf[4];
                ldsm4(bhf, bhb + (rowB + p * 16) * 80 + kb * 32 + colB);
                ldsm4(blf, blb + (rowB + p * 16) * 80 + kb * 32 + colB);
#pragma unroll
                for (int mt = 0; mt < 2; mt++) {
#pragma unroll
                    for (int sub = 0; sub < 2; sub++) {
                        float* c = &acc[(mt * 4 + p * 2 + sub) * 4];
                        mma16816(c, ah[mt], bhf[sub * 2], bhf[sub * 2 + 1]);
                        mma16816(c, al[mt], bhf[sub * 2], bhf[sub * 2 + 1]);
                        mma16816(c, ah[mt], blf[sub * 2], blf[sub * 2 + 1]);
                    }
                }
            }
        }
        __syncthreads();
        if (kt + 2 < ksteps) { load_stage(s, (kt + 2) * 32); CP_COMMIT; }
    }

    // epilogue
#pragma unroll
    for (int mt = 0; mt < 2; mt++) {
#pragma unroll
        for (int nt = 0; nt < 4; nt++) {
            const float* c = &acc[(mt * 4 + nt) * 4];
            int row = bm + wm * 32 + mt * 16 + (lane >> 2);
            int col = bn + wn * 32 + nt * 8 + (lane & 3) * 2;
            float b0 = 0.f, b1 = 0.f;
            if (bias) { b0 = bias[col]; b1 = bias[col + 1]; }
            float2 r0 = make_float2(c[0] + b0, c[1] + b1);
            float2 r1 = make_float2(c[2] + b0, c[3] + b1);
            *(float2*)&C[(size_t)row * N + col] = r0;
            *(float2*)&C[(size_t)(row + 8) * N + col] = r1;
        }
    }
}

// =================================================================
// Mask resize + count
// =================================================================
__global__ void resize_mask(const float* __restrict__ mask,
                            float* __restrict__ m, float* __restrict__ cnt)
{
    int i = threadIdx.x;
    int r = i >> 5, c = i & 31;
    float mv = mask[(r * 2) * 64 + c * 2];
    m[i] = mv;
    __shared__ float red[1024];
    red[i] = mv;
    __syncthreads();
    for (int s = 512; s > 0; s >>= 1) {
        if (i < s) red[i] += red[i + s];
        __syncthreads();
    }
    if (i == 0) cnt[0] = red[0];
}

// =================================================================
// AdaIN stats / apply
// =================================================================
__global__ __launch_bounds__(256) void adain_stats(
    const float* __restrict__ kbuf, const float* __restrict__ vbuf,
    const float* __restrict__ m, const float* __restrict__ cntp,
    float* __restrict__ scaleArr, float* __restrict__ shiftArr)
{
    int tensor = blockIdx.x >> 9;
    int ch     = blockIdx.x & 511;
    const float* T    = tensor ? vbuf : kbuf;
    const float* ref  = T + ch;
    const float* feat = T + (size_t)N_ * QD_ + ch;

    float rs = 0.f, rss = 0.f, fs = 0.f, fss = 0.f;
    for (int i = threadIdx.x; i < N_; i += 256) {
        float rv = ref [(size_t)i * QD_];
        float fv = feat[(size_t)i * QD_];
        float mv = m[i];
        rs += rv; rss += rv * rv;
        fs += mv * fv; fss += mv * fv * fv;
    }
    __shared__ float4 red[256];
    red[threadIdx.x] = make_float4(rs, rss, fs, fss);
    __syncthreads();
    for (int s = 128; s > 0; s >>= 1) {
        if (threadIdx.x < s) {
            float4 a = red[threadIdx.x], b = red[threadIdx.x + s];
            red[threadIdx.x] = make_float4(a.x + b.x, a.y + b.y, a.z + b.z, a.w + b.w);
        }
        __syncthreads();
    }
    if (threadIdx.x == 0) {
        float cnt = cntp[0];
        float4 r = red[0];
        float ref_mean = r.x * (1.0f / N_);
        float ref_var  = (r.y - (float)N_ * ref_mean * ref_mean) * (1.0f / (N_ - 1));
        float ref_std  = sqrtf(fmaxf(ref_var, 0.f));
        float f_mean   = r.z / cnt;
        float f_var    = (r.w - cnt * f_mean * f_mean) / (cnt - 1.0f);
        float f_std    = sqrtf(fmaxf(f_var, 0.f));
        float sc = ref_std / f_std;
        scaleArr[blockIdx.x] = sc;
        shiftArr[blockIdx.x] = ref_mean - f_mean * sc;
    }
}

__global__ void adain_apply(float* __restrict__ kbuf, float* __restrict__ vbuf,
                            const float* __restrict__ m,
                            const float* __restrict__ scaleArr,
                            const float* __restrict__ shiftArr)
{
    int row    = blockIdx.x & 1023;
    int tensor = blockIdx.x >> 10;
    if (m[row] < 0.5f) return;
    float* T = tensor ? vbuf : kbuf;
    int ch = threadIdx.x;
    float sc = scaleArr[tensor * QD_ + ch];
    float sh = shiftArr[tensor * QD_ + ch];
    size_t off = (size_t)(N_ + row) * QD_ + ch;
    T[off] = fmaf(T[off], sc, sh);
}

// =================================================================
// Flash attention via mma.sync, no-max softmax, split-bf16 precision.
// grid (16 qtiles, 16 bh, 2 kvsplit), 128 thr (4 warps, 16 q-rows each).
// Per 64-key tile: S=QK^T (3 mma products), p=exp(s*scale)*maskflag,
// p split to bf16 hi/lo in-register, O += P V (3 mma products).
// =================================================================
#define AQH 0
#define AQL 9216
#define ATS(s) (18432 + (s) * 36864)
#define ATTN_SMEM 92160

__global__ __launch_bounds__(128) void attn_mma(
    const __nv_bfloat16* __restrict__ qhi, const __nv_bfloat16* __restrict__ qlo,
    const __nv_bfloat16* __restrict__ khi, const __nv_bfloat16* __restrict__ klo,
    const __nv_bfloat16* __restrict__ vhi, const __nv_bfloat16* __restrict__ vlo,
    const float* __restrict__ m,
    float* __restrict__ part, float* __restrict__ lsum)
{
    extern __shared__ __align__(16) char sma[];
    const uint32_t sb = smem_u32(sma);
    const int tid = threadIdx.x, wid = tid >> 5, lane = tid & 31;
    const int bh = blockIdx.y, b = bh >> 3, h = bh & 7;
    const int z = blockIdx.z;
    const int q0 = blockIdx.x * 64;
    const int grp = lane >> 3, lr = lane & 7;

    // ---- Q tile (hi/lo) via cp.async ----
#pragma unroll
    for (int i = 0; i < 8; i++) {
        int c = tid + i * 128;
        int p = c >> 9, r = (c >> 3) & 63, col = c & 7;
        const __nv_bfloat16* src = (p ? qlo : qhi) + (size_t)(b * N_ + q0 + r) * QD_ + h * DH_ + col * 8;
        cp16(sb + (p ? AQL : AQH) + r * 144 + col * 16, src);
    }

    auto load_tile = [&](int s, int tileIdx) {
        int j0 = tileIdx * 64;
        int grow = (j0 < N_) ? (b * N_ + j0) : (j0 - N_);
        uint32_t tb = sb + ATS(s);
#pragma unroll
        for (int i = 0; i < 16; i++) {
            int c = tid + i * 128;
            int mt = c >> 9, r = (c >> 3) & 63, col = c & 7;
            const __nv_bfloat16* srcb = (mt == 0) ? khi : (mt == 1) ? klo : (mt == 2) ? vhi : vlo;
            cp16(tb + mt * 9216 + r * 144 + col * 16,
                 srcb + (size_t)(grow + r) * QD_ + h * DH_ + col * 8);
        }
    };

    load_tile(0, z * 16);     CP_COMMIT;   // group0: Q + T0
    load_tile(1, z * 16 + 1); CP_COMMIT;   // group1: T1
    CP_WAIT1;
    __syncthreads();

    // ---- Q fragments (4 k16 tiles x 4 regs, hi & lo) ----
    uint32_t qh[16], ql[16];
    {
        uint32_t base = sb + AQH + (wid * 16 + (lane & 15)) * 144 + (lane >> 4) * 16;
#pragma unroll
        for (int k16 = 0; k16 < 4; k16++) ldsm4(&qh[k16 * 4], base + k16 * 32);
        base += (AQL - AQH);
#pragma unroll
        for (int k16 = 0; k16 < 4; k16++) ldsm4(&ql[k16 * 4], base + k16 * 32);
    }

    const int r4 = lane >> 2;
    const int qrow = q0 + wid * 16 + r4;
    float flag0 = 1.f, flag1 = 1.f;
    if (b == 1 && z == 1) {
        flag0 = (m[qrow]     < 0.5f) ? 0.f : 1.f;
        flag1 = (m[qrow + 8] < 0.5f) ? 0.f : 1.f;
    }

    float o[32];
#pragma unroll
    for (int i = 0; i < 32; i++) o[i] = 0.f;
    float l0 = 0.f, l1 = 0.f;

    const int rowKb = ((grp >> 1) << 3) + lr;
    const int colK  = (grp & 1) * 16;
    const int rowVb = ((grp & 1) << 3) + lr;
    const int colV  = (grp >> 1) * 16;

    for (int kt = 0; kt < 16; kt++) {
        const int s = kt & 1;
        if (kt > 0) {
            if (kt == 15) { CP_WAIT0; } else { CP_WAIT1; }
            __syncthreads();
        }
        const uint32_t khb = sb + ATS(s);
        const uint32_t klb = khb + 9216;
        const uint32_t vhb = khb + 18432;
        const uint32_t vlb = khb + 27648;

#pragma unroll
        for (int kk = 0; kk < 4; kk++) {
            float s0[4] = {0.f, 0.f, 0.f, 0.f};
            float s1[4] = {0.f, 0.f, 0.f, 0.f};
            const uint32_t kro = (kk * 16 + rowKb) * 144 + colK;
#pragma unroll
            for (int k16 = 0; k16 < 4; k16++) {
                uint32_t bhf[4], blf[4];
                ldsm4(bhf, khb + kro + k16 * 32);
                ldsm4(blf, klb + kro + k16 * 32);
                mma16816(s0, &qh[k16 * 4], bhf[0], bhf[1]);
                mma16816(s1, &qh[k16 * 4], bhf[2], bhf[3]);
                mma16816(s0, &ql[k16 * 4], bhf[0], bhf[1]);
                mma16816(s1, &ql[k16 * 4], bhf[2], bhf[3]);
                mma16816(s0, &qh[k16 * 4], blf[0], blf[1]);
                mma16816(s1, &qh[k16 * 4], blf[2], blf[3]);
            }
            s0[0] = __expf(s0[0] * SCALE_) * flag0;
            s0[1] = __expf(s0[1] * SCALE_) * flag0;
            s0[2] = __expf(s0[2] * SCALE_) * flag1;
            s0[3] = __expf(s0[3] * SCALE_) * flag1;
            s1[0] = __expf(s1[0] * SCALE_) * flag0;
            s1[1] = __expf(s1[1] * SCALE_) * flag0;
            s1[2] = __expf(s1[2] * SCALE_) * flag1;
            s1[3] = __expf(s1[3] * SCALE_) * flag1;
            l0 += s0[0] + s0[1] + s1[0] + s1[1];
            l1 += s0[2] + s0[3] + s1[2] + s1[3];

            uint32_t ph[4], pl[4];
            ph[0] = pkbf(s0[0], s0[1]);
            pl[0] = pkbf(s0[0] - lo16f(ph[0]), s0[1] - hi16f(ph[0]));
            ph[1] = pkbf(s0[2], s0[3]);
            pl[1] = pkbf(s0[2] - lo16f(ph[1]), s0[3] - hi16f(ph[1]));
            ph[2] = pkbf(s1[0], s1[1]);
            pl[2] = pkbf(s1[0] - lo16f(ph[2]), s1[1] - hi16f(ph[2]));
            ph[3] = pkbf(s1[2], s1[3]);
            pl[3] = pkbf(s1[2] - lo16f(ph[3]), s1[3] - hi16f(ph[3]));

            const uint32_t vro = (kk * 16 + rowVb) * 144 + colV;
#pragma unroll
            for (int dp = 0; dp < 4; dp++) {
                uint32_t vhf[4], vlf[4];
                ldsm4t(vhf, vhb + vro + dp * 32);
                ldsm4t(vlf, vlb + vro + dp * 32);
                mma16816(&o[dp * 8],     ph, vhf[0], vhf[1]);
                mma16816(&o[dp * 8 + 4], ph, vhf[2], vhf[3]);
                mma16816(&o[dp * 8],     pl, vhf[0], vhf[1]);
                mma16816(&o[dp * 8 + 4], pl, vhf[2], vhf[3]);
                mma16816(&o[dp * 8],     ph, vlf[0], vlf[1]);
                mma16816(&o[dp * 8 + 4], ph, vlf[2], vlf[3]);
            }
        }
        __syncthreads();
        if (kt + 2 < 16) { load_tile(s, z * 16 + kt + 2); CP_COMMIT; }
    }

    // ---- epilogue: partial O and l ----
    l0 += __shfl_xor_sync(0xffffffffu, l0, 1);
    l0 += __shfl_xor_sync(0xffffffffu, l0, 2);
    l1 += __shfl_xor_sync(0xffffffffu, l1, 1);
    l1 += __shfl_xor_sync(0xffffffffu, l1, 2);

    float* pd = part + (size_t)(z * 16 + bh) * N_ * DH_;
#pragma unroll
    for (int nt = 0; nt < 8; nt++) {
        int col = nt * 8 + (lane & 3) * 2;
        *(float2*)&pd[(size_t)qrow * DH_ + col]       = make_float2(o[nt * 4 + 0], o[nt * 4 + 1]);
        *(float2*)&pd[(size_t)(qrow + 8) * DH_ + col] = make_float2(o[nt * 4 + 2], o[nt * 4 + 3]);
    }
    if ((lane & 3) == 0) {
        lsum[(z * 16 + bh) * N_ + qrow]     = l0;
        lsum[(z * 16 + bh) * N_ + qrow + 8] = l1;
    }
}

// =================================================================
// Combine kv-split partials -> ao[b, n, h*64+d]
// =================================================================
__global__ __launch_bounds__(128) void attn_reduce(
    const float* __restrict__ part, const float* __restrict__ lsum,
    float* __restrict__ ao)
{
    int row = blockIdx.x * 128 + threadIdx.x;   // [0, 16*1024)
    int bh = row >> 10, qi = row & 1023;
    int b = bh >> 3, h = bh & 7;

    float l = 0.f;
#pragma unroll
    for (int z = 0; z < KVSPLIT; z++) l += lsum[(z * 16 + bh) * N_ + qi];
    float inv = 1.0f / l;

    float* dst = ao + ((size_t)(b * N_ + qi) * QD_ + h * DH_);
#pragma unroll
    for (int d4 = 0; d4 < 16; d4++) {
        float4 acc = make_float4(0.f, 0.f, 0.f, 0.f);
#pragma unroll
        for (int z = 0; z < KVSPLIT; z++) {
            const float4 p4 = ((const float4*)(part +
                ((size_t)(z * 16 + bh) * N_ + qi) * DH_))[d4];
            acc.x += p4.x; acc.y += p4.y; acc.z += p4.z; acc.w += p4.w;
        }
        dst[d4*4+0] = acc.x * inv; dst[d4*4+1] = acc.y * inv;
        dst[d4*4+2] = acc.z * inv; dst[d4*4+3] = acc.w * inv;
    }
}

// =================================================================
extern "C" void kernel_launch(void* const* d_in, const int* in_sizes, int n_in,
                              void* d_out, int out_size)
{
    const float* x    = (const float*)d_in[0];
    const float* mask = (const float*)d_in[1];
    const float* Wq   = (const float*)d_in[2];
    const float* Wk   = (const float*)d_in[3];
    const float* Wv   = (const float*)d_in[4];
    const float* Wo   = (const float*)d_in[5];
    const float* bo   = (const float*)d_in[6];

    float *q, *k, *v, *ao, *m, *cnt, *sc, *sh, *prt, *lsm;
    __nv_bfloat16 *xhi, *xlo, *whi, *wlo, *qhi, *qlo, *khi, *klo, *vhi, *vlo, *aohi, *aolo;
    cudaGetSymbolAddress((void**)&q,    g_q);
    cudaGetSymbolAddress((void**)&k,    g_k);
    cudaGetSymbolAddress((void**)&v,    g_v);
    cudaGetSymbolAddress((void**)&ao,   g_ao);
    cudaGetSymbolAddress((void**)&m,    g_m);
    cudaGetSymbolAddress((void**)&cnt,  g_cnt);
    cudaGetSymbolAddress((void**)&sc,   g_scale);
    cudaGetSymbolAddress((void**)&sh,   g_shift);
    cudaGetSymbolAddress((void**)&prt,  g_part);
    cudaGetSymbolAddress((void**)&lsm,  g_lsum);
    cudaGetSymbolAddress((void**)&xhi,  g_xhi);
    cudaGetSymbolAddress((void**)&xlo,  g_xlo);
    cudaGetSymbolAddress((void**)&whi,  g_whi);
    cudaGetSymbolAddress((void**)&wlo,  g_wlo);
    cudaGetSymbolAddress((void**)&qhi,  g_qhi);
    cudaGetSymbolAddress((void**)&qlo,  g_qlo);
    cudaGetSymbolAddress((void**)&khi,  g_khi);
    cudaGetSymbolAddress((void**)&klo,  g_klo);
    cudaGetSymbolAddress((void**)&vhi,  g_vhi);
    cudaGetSymbolAddress((void**)&vlo,  g_vlo);
    cudaGetSymbolAddress((void**)&aohi, g_aohi);
    cudaGetSymbolAddress((void**)&aolo, g_aolo);

    cudaFuncSetAttribute(gemm_mma, cudaFuncAttributeMaxDynamicSharedMemorySize, GEMM_SMEM);
    cudaFuncSetAttribute(attn_mma, cudaFuncAttributeMaxDynamicSharedMemorySize, ATTN_SMEM);

    const int M = B_ * N_;       // 2048
    const int NXE = M * QD_;     // 1048576
    const int NWE = QD_ * QD_;   // 262144
    const int WS = QD_ * QD_;

    cvt_split<<<(NXE + 255) / 256, 256>>>(x,  xhi, xlo, NXE);
    cvt_split<<<(NWE + 255) / 256, 256>>>(Wq, whi + 0*WS, wlo + 0*WS, NWE);
    cvt_split<<<(NWE + 255) / 256, 256>>>(Wk, whi + 1*WS, wlo + 1*WS, NWE);
    cvt_split<<<(NWE + 255) / 256, 256>>>(Wv, whi + 2*WS, wlo + 2*WS, NWE);
    cvt_split<<<(NWE + 255) / 256, 256>>>(Wo, whi + 3*WS, wlo + 3*WS, NWE);

    dim3 gg(QD_ / 64, M / 128);   // (8,16)
    gemm_mma<<<gg, 256, GEMM_SMEM>>>(xhi, xlo, whi + 0*WS, wlo + 0*WS, nullptr, q, M, QD_, QD_);
    gemm_mma<<<gg, 256, GEMM_SMEM>>>(xhi, xlo, whi + 1*WS, wlo + 1*WS, nullptr, k, M, QD_, QD_);
    gemm_mma<<<gg, 256, GEMM_SMEM>>>(xhi, xlo, whi + 2*WS, wlo + 2*WS, nullptr, v, M, QD_, QD_);

    resize_mask<<<1, 1024>>>(mask, m, cnt);
    adain_stats<<<1024, 256>>>(k, v, m, cnt, sc, sh);
    adain_apply<<<2048, 512>>>(k, v, m, sc, sh);

    cvt_split<<<(NXE + 255) / 256, 256>>>(q, qhi, qlo, NXE);
    cvt_split<<<(NXE + 255) / 256, 256>>>(k, khi, klo, NXE);
    cvt_split<<<(NXE + 255) / 256, 256>>>(v, vhi, vlo, NXE);

    attn_mma<<<dim3(16, 16, KVSPLIT), 128, ATTN_SMEM>>>(qhi, qlo, khi, klo, vhi, vlo, m, prt, lsm);
    attn_reduce<<<128, 128>>>(prt, lsm, ao);

    cvt_split<<<(NXE + 255) / 256, 256>>>(ao, aohi, aolo, NXE);
    gemm_mma<<<gg, 256, GEMM_SMEM>>>(aohi, aolo, whi + 3*WS, wlo + 3*WS, bo, (float*)d_out, M, QD_, QD_);
}